// round 3
// baseline (speedup 1.0000x reference)
#include <cuda_runtime.h>
#include <cuda_bf16.h>
#include <math.h>
#include <stdint.h>

// Problem constants
#define NN   512
#define LL   64
#define DH   256
#define DX   64
#define QQ   8192
#define NTYP 16
#define NMEM 262144
#define NSEG (NN*LL)        // 32768

// Scratch (device globals; no allocation allowed)
__device__ __align__(16) float g_xsum[NSEG * DX];       // 8 MB
__device__ __align__(16) float g_wv  [QQ * DH];         // 8 MB
__device__ __align__(16) float g_w2  [2 * DH * DH];     // 512x256 = WqT @ Wk
__device__ float g_u   [2 * DH];          // WqT @ bk
__device__ float g_b2  [DH];              // bq @ Wk
__device__ float g_cq;                    // bk . bq
__device__ int   g_em  [NN];
__device__ int   g_acc_cnt;

// ---------------------------------------------------------------------------
// Kernel 0: tiny init (xsum is zeroed by cudaMemsetAsync)
// ---------------------------------------------------------------------------
__global__ void init_kernel() {
    int tid = threadIdx.x;   // 512
    g_em[tid] = 0x7fffffff;
    if (tid == 0) g_acc_cnt = 0;
}

// ---------------------------------------------------------------------------
// Kernel 1: x_sum = segment_sum(tok_emb[mem], grp)
// 4,194,304 (entry,quad) tasks; each thread does 4 with independent chains.
// red.global.add.v4.f32 quarters the atomic op count.
// ---------------------------------------------------------------------------
#define SC_NT (NMEM * 16 / 4)   // 1,048,576 threads
__global__ __launch_bounds__(256)
void scatter_kernel(const float* __restrict__ tok_emb,
                    const int*   __restrict__ mem,
                    const int*   __restrict__ grp) {
    int t = blockIdx.x * 256 + threadIdx.x;
    int   gg[4], qd[4];
    float4 v[4];
    #pragma unroll
    for (int k = 0; k < 4; k++) {
        int task = t + k * SC_NT;
        int e = task >> 4;
        qd[k] = task & 15;
        int tok = __ldg(&mem[e]);
        gg[k]  = __ldg(&grp[e]);
        v[k] = __ldg(reinterpret_cast<const float4*>(tok_emb) + tok * 16 + qd[k]);
    }
    #pragma unroll
    for (int k = 0; k < 4; k++) {
        float* dst = &g_xsum[(size_t)gg[k] * DX + qd[k] * 4];
        asm volatile("red.global.add.v4.f32 [%0], {%1, %2, %3, %4};"
                     :: "l"(dst), "f"(v[k].x), "f"(v[k].y), "f"(v[k].z), "f"(v[k].w)
                     : "memory");
    }
}

// ---------------------------------------------------------------------------
// Kernel 2: W2[k,e] = sum_d Wq[d,k] * Wk[d,e]   (512 x 256, K=256)
// ---------------------------------------------------------------------------
__global__ __launch_bounds__(256)
void w2_kernel(const float* __restrict__ Wq, const float* __restrict__ Wk) {
    __shared__ float s_wq[DH][16];      // [d][kl]
    int tid = threadIdx.x;
    int k0 = blockIdx.x * 16;
    #pragma unroll
    for (int r = 0; r < 16; r++) {
        int fid = tid + r * 256;        // 0..4095
        int d = fid >> 4, kl = fid & 15;
        s_wq[d][kl] = __ldg(&Wq[(size_t)d * (2 * DH) + k0 + kl]);
    }
    __syncthreads();
    float acc[16] = {};
    int e = tid;
    #pragma unroll 4
    for (int d = 0; d < DH; d++) {
        float wkv = __ldg(&Wk[(size_t)d * DH + e]);
        #pragma unroll
        for (int kl = 0; kl < 16; kl++) acc[kl] += s_wq[d][kl] * wkv;
    }
    #pragma unroll
    for (int kl = 0; kl < 16; kl++)
        g_w2[(size_t)(k0 + kl) * DH + e] = acc[kl];
}

// ---------------------------------------------------------------------------
// Kernel 3: u[k] = Wq^T bk ; b2[e] = bq Wk ; cq = bk.bq
// ---------------------------------------------------------------------------
__global__ __launch_bounds__(512)
void vec_kernel(const float* __restrict__ Wq, const float* __restrict__ Wk,
                const float* __restrict__ bq, const float* __restrict__ bk) {
    int tid = threadIdx.x;
    float ua = 0.f;
    for (int d = 0; d < DH; d++) ua += __ldg(&bk[d]) * __ldg(&Wq[(size_t)d * (2 * DH) + tid]);
    g_u[tid] = ua;
    if (tid < DH) {
        float b2 = 0.f;
        for (int d = 0; d < DH; d++) b2 += __ldg(&bq[d]) * __ldg(&Wk[(size_t)d * DH + tid]);
        g_b2[tid] = b2;
    }
    if (tid == 0) {
        float c = 0.f;
        for (int d = 0; d < DH; d++) c += __ldg(&bk[d]) * __ldg(&bq[d]);
        g_cq = c;
    }
}

// ---------------------------------------------------------------------------
// Kernel 4: fused gather-GEMM: wv[q,e] = sum_k q_in[q,k]*W2[k,e] + b2[e]
// BM=BN=128, BK=16, 256 threads, 8x8 microtile, double-buffered.
// ---------------------------------------------------------------------------
__global__ __launch_bounds__(256)
void gemm_fused(const float* __restrict__ h_grp,
                const int* __restrict__ idx,
                const int* __restrict__ src,
                const int* __restrict__ dst) {
    __shared__ float As[2][16][128];
    __shared__ float Bs[2][16][128];
    __shared__ int   sOff[2][128];

    const int tid  = threadIdx.x;
    const int row0 = blockIdx.y * 128;
    const int col0 = blockIdx.x * 128;

    if (tid < 128) {
        int q = row0 + tid;
        int i = __ldg(&idx[q]);
        sOff[0][tid] = (i * LL + __ldg(&src[q])) * DH;
        sOff[1][tid] = (i * LL + __ldg(&dst[q])) * DH;
    }
    __syncthreads();

    const int am0 = tid >> 2,          akc0 = (tid & 3) * 4;
    const int am1 = (tid + 256) >> 2,  akc1 = (tid & 3) * 4;
    const int bk0 = tid >> 5,          bc0 = (tid & 31) * 4;
    const int bk1 = (tid + 256) >> 5,  bc1 = (tid & 31) * 4;

    float4 rA0, rA1, rB0, rB1;

    auto loadTile = [&](int t) {
        int k0 = t * 16;
        int half = k0 >> 8;
        int kb = k0 & 255;
        rA0 = *reinterpret_cast<const float4*>(h_grp + sOff[half][am0] + kb + akc0);
        rA1 = *reinterpret_cast<const float4*>(h_grp + sOff[half][am1] + kb + akc1);
        rB0 = *reinterpret_cast<const float4*>(&g_w2[(size_t)(k0 + bk0) * DH + col0 + bc0]);
        rB1 = *reinterpret_cast<const float4*>(&g_w2[(size_t)(k0 + bk1) * DH + col0 + bc1]);
    };
    auto storeTile = [&](int buf) {
        As[buf][akc0 + 0][am0] = rA0.x; As[buf][akc0 + 1][am0] = rA0.y;
        As[buf][akc0 + 2][am0] = rA0.z; As[buf][akc0 + 3][am0] = rA0.w;
        As[buf][akc1 + 0][am1] = rA1.x; As[buf][akc1 + 1][am1] = rA1.y;
        As[buf][akc1 + 2][am1] = rA1.z; As[buf][akc1 + 3][am1] = rA1.w;
        *reinterpret_cast<float4*>(&Bs[buf][bk0][bc0]) = rB0;
        *reinterpret_cast<float4*>(&Bs[buf][bk1][bc1]) = rB1;
    };

    loadTile(0);
    storeTile(0);
    __syncthreads();

    float acc[8][8] = {};
    const int ty8 = (tid >> 4) * 8;
    const int tx8 = (tid & 15) * 8;

    for (int t = 0; t < 32; t++) {
        int buf = t & 1;
        if (t < 31) loadTile(t + 1);
        #pragma unroll
        for (int k = 0; k < 16; k++) {
            float4 a0 = *reinterpret_cast<const float4*>(&As[buf][k][ty8]);
            float4 a1 = *reinterpret_cast<const float4*>(&As[buf][k][ty8 + 4]);
            float4 b0 = *reinterpret_cast<const float4*>(&Bs[buf][k][tx8]);
            float4 b1 = *reinterpret_cast<const float4*>(&Bs[buf][k][tx8 + 4]);
            float av[8] = {a0.x, a0.y, a0.z, a0.w, a1.x, a1.y, a1.z, a1.w};
            float bv[8] = {b0.x, b0.y, b0.z, b0.w, b1.x, b1.y, b1.z, b1.w};
            #pragma unroll
            for (int i = 0; i < 8; i++)
                #pragma unroll
                for (int j = 0; j < 8; j++)
                    acc[i][j] += av[i] * bv[j];
        }
        if (t < 31) {
            storeTile(buf ^ 1);
            __syncthreads();
        }
    }

    float bb[8];
    #pragma unroll
    for (int j = 0; j < 8; j++) bb[j] = g_b2[col0 + tx8 + j];
    #pragma unroll
    for (int i = 0; i < 8; i++) {
        int q = row0 + ty8 + i;
        float* cr = g_wv + (size_t)q * DH + col0 + tx8;
        float4 o0 = {acc[i][0] + bb[0], acc[i][1] + bb[1], acc[i][2] + bb[2], acc[i][3] + bb[3]};
        float4 o1 = {acc[i][4] + bb[4], acc[i][5] + bb[5], acc[i][6] + bb[6], acc[i][7] + bb[7]};
        *reinterpret_cast<float4*>(cr)     = o0;
        *reinterpret_cast<float4*>(cr + 4) = o1;
    }
}

// ---------------------------------------------------------------------------
// Kernel 5: block-per-GROUP attention + rel head + metrics.
// idx is sorted: binary search the query range of group n, stage h rows,
// x_grp and mask in smem once, then loop queries out of smem.
// ---------------------------------------------------------------------------
__device__ __forceinline__ int lbound(const int* __restrict__ a, int n, int key) {
    int lo = 0, hi = n;
    while (lo < hi) { int m = (lo + hi) >> 1; if (__ldg(&a[m]) < key) lo = m + 1; else hi = m; }
    return lo;
}

#define ATTN_SMEM_BYTES ((16384 + 4096 + 256 + 256 + 64*4 + 8) * 4 + (64 + 16) * 4)

__global__ __launch_bounds__(256)
void attn_kernel(const float* __restrict__ h_grp,
                 const float* __restrict__ Wrel,
                 const float* __restrict__ brel,
                 const int*   __restrict__ idx,
                 const int*   __restrict__ src,
                 const int*   __restrict__ dst,
                 const int*   __restrict__ pos2grp,
                 const int*   __restrict__ msk,
                 const int*   __restrict__ typ,
                 float* __restrict__ out_logit) {
    extern __shared__ float sm[];
    float* s_h    = sm;                  // 16384
    float* s_xg   = s_h   + 16384;       // 4096
    float* s_wv   = s_xg  + 4096;        // 256
    float* s_part = s_wv  + 256;         // 256
    float* s_s    = s_part+ 256;         // 64
    float* s_a    = s_s   + 64;          // 64
    float* s_msk  = s_a   + 64;          // 64
    float* s_attn = s_msk + 64;          // 64
    float* s_red  = s_attn+ 64;          // 8
    int*   s_g    = (int*)(s_red + 8);   // 64
    int*   s_eq   = s_g + 64;            // 16

    const int n    = blockIdx.x;
    const int tid  = threadIdx.x;     // 256
    const int lane = tid & 31;
    const int w    = tid >> 5;        // 8 warps

    int lo = lbound(idx, QQ, n);
    int hi = lbound(idx, QQ, n + 1);
    if (lo >= hi) return;

    // stage h rows (64x256 floats)
    {
        const float4* hb4 = reinterpret_cast<const float4*>(h_grp + (size_t)n * LL * DH);
        float4* sh4 = reinterpret_cast<float4*>(s_h);
        #pragma unroll
        for (int k = 0; k < 16; k++) sh4[tid + k * 256] = __ldg(hb4 + tid + k * 256);
    }
    if (tid < LL) {
        s_g[tid]   = __ldg(&pos2grp[n * LL + tid]);
        s_msk[tid] = (__ldg(&msk[n * LL + tid]) == 0) ? -INFINITY : 0.f;
    }
    __syncthreads();

    // gather x_grp rows (64x64 floats)
    {
        float4* sx4 = reinterpret_cast<float4*>(s_xg);
        const float4* xs4 = reinterpret_cast<const float4*>(g_xsum);
        #pragma unroll
        for (int k = 0; k < 4; k++) {
            int v = tid + k * 256;
            int row = v >> 4, c4 = v & 15;
            sx4[v] = xs4[(size_t)s_g[row] * 16 + c4];
        }
    }
    __syncthreads();

    int accLocal = 0, emLocal = 1;

    for (int q = lo; q < hi; q++) {
        const int sp = __ldg(&src[q]);
        const int dp = __ldg(&dst[q]);
        s_wv[tid] = __ldg(&g_wv[(size_t)q * DH + tid]);
        float v1 = s_h[sp * DH + tid];
        float v2 = s_h[dp * DH + tid];
        float cp = v1 * __ldg(&g_u[tid]) + v2 * __ldg(&g_u[tid + DH]);
        #pragma unroll
        for (int o = 16; o > 0; o >>= 1) cp += __shfl_xor_sync(0xffffffffu, cp, o);
        if (lane == 0) s_red[w] = cp;
        __syncthreads();

        float c = g_cq;
        #pragma unroll
        for (int r = 0; r < 8; r++) c += s_red[r];

        // scores: warp w handles l = w*8 .. w*8+7 from smem
        #pragma unroll
        for (int il = 0; il < 8; il++) {
            int l = (w << 3) + il;
            const float* hr = s_h + l * DH;
            float p = 0.f;
            #pragma unroll
            for (int e = 0; e < DH; e += 32) p += hr[e + lane] * s_wv[e + lane];
            #pragma unroll
            for (int o = 16; o > 0; o >>= 1) p += __shfl_xor_sync(0xffffffffu, p, o);
            if (lane == 0) s_s[l] = (p + c) * 0.0625f + s_msk[l];
        }
        __syncthreads();

        // softmax over 64 by warp 0
        if (w == 0) {
            float a0 = s_s[lane], a1 = s_s[lane + 32];
            float m = fmaxf(a0, a1);
            #pragma unroll
            for (int o = 16; o > 0; o >>= 1) m = fmaxf(m, __shfl_xor_sync(0xffffffffu, m, o));
            float e0 = __expf(a0 - m), e1 = __expf(a1 - m);
            float ss = e0 + e1;
            #pragma unroll
            for (int o = 16; o > 0; o >>= 1) ss += __shfl_xor_sync(0xffffffffu, ss, o);
            float inv = 1.f / ss;
            s_a[lane] = e0 * inv; s_a[lane + 32] = e1 * inv;
        }
        __syncthreads();

        // attn[j] = sum_l a[l] * x_grp[l, j]
        {
            int j = tid & 63, part = tid >> 6;
            float ap = 0.f;
            #pragma unroll
            for (int li = 0; li < 16; li++) {
                int l = (part << 4) + li;
                ap += s_a[l] * s_xg[l * DX + j];
            }
            s_part[tid] = ap;
        }
        __syncthreads();
        if (tid < DX) s_attn[tid] = s_part[tid] + s_part[tid + 64] + s_part[tid + 128] + s_part[tid + 192];
        __syncthreads();

        // rel head: warp w computes t = 2w, 2w+1 ; dot length 576
        const float* hs = s_h + sp * DH;
        const float* hd = s_h + dp * DH;
        #pragma unroll
        for (int tt = 0; tt < 2; tt++) {
            int t = (w << 1) + tt;
            const float* wr = Wrel + (size_t)t * (2 * DH + DX);
            float p = 0.f;
            #pragma unroll
            for (int k = 0; k < DH; k += 32) p += hs[k + lane] * __ldg(&wr[k + lane]);
            #pragma unroll
            for (int k = 0; k < DH; k += 32) p += hd[k + lane] * __ldg(&wr[DH + k + lane]);
            p += s_attn[lane] * __ldg(&wr[2 * DH + lane]);
            p += s_attn[lane + 32] * __ldg(&wr[2 * DH + 32 + lane]);
            #pragma unroll
            for (int o = 16; o > 0; o >>= 1) p += __shfl_xor_sync(0xffffffffu, p, o);
            if (lane == 0) {
                p += __ldg(&brel[t]);
                out_logit[(size_t)q * NTYP + t] = p;
                int gt = (p > 0.f) ? 1 : 0;
                int ty = (__ldg(&typ[q * NTYP + t]) > 0) ? 1 : 0;
                s_eq[t] = (gt == ty) ? 1 : 0;
            }
        }
        __syncthreads();
        if (tid == 0) {
            int cnt = 0, all = 1;
            #pragma unroll
            for (int t = 0; t < NTYP; t++) { cnt += s_eq[t]; all &= s_eq[t]; }
            accLocal += cnt;
            emLocal &= all;
        }
        __syncthreads();
    }

    if (tid == 0) {
        atomicAdd(&g_acc_cnt, accLocal);
        g_em[n] = emLocal;
    }
}

// ---------------------------------------------------------------------------
// Kernel 6: finalize scalars. out layout: [logit(131072), acc, emr, em(512)]
// ---------------------------------------------------------------------------
__global__ __launch_bounds__(512)
void finalize_kernel(float* __restrict__ out) {
    __shared__ float s_red[16];
    int tid = threadIdx.x;            // 512
    int lane = tid & 31, w = tid >> 5;
    float e = (float)g_em[tid];
    out[QQ * NTYP + 2 + tid] = e;
    float p = e;
    #pragma unroll
    for (int o = 16; o > 0; o >>= 1) p += __shfl_xor_sync(0xffffffffu, p, o);
    if (lane == 0) s_red[w] = p;
    __syncthreads();
    if (tid == 0) {
        float sum = 0.f;
        #pragma unroll
        for (int r = 0; r < 16; r++) sum += s_red[r];
        out[QQ * NTYP + 0] = (float)g_acc_cnt / (float)(QQ * NTYP);
        out[QQ * NTYP + 1] = sum / (float)NN;
    }
}

// ---------------------------------------------------------------------------
extern "C" void kernel_launch(void* const* d_in, const int* in_sizes, int n_in,
                              void* d_out, int out_size) {
    const float* h_grp   = (const float*)d_in[0];
    const float* tok_emb = (const float*)d_in[1];
    const float* Wq      = (const float*)d_in[2];
    const float* bq      = (const float*)d_in[3];
    const float* Wk      = (const float*)d_in[4];
    const float* bk      = (const float*)d_in[5];
    const float* Wrel    = (const float*)d_in[6];
    const float* brel    = (const float*)d_in[7];
    const int*   mem     = (const int*)d_in[8];
    const int*   grp     = (const int*)d_in[9];
    const int*   pos2grp = (const int*)d_in[10];
    const int*   msk     = (const int*)d_in[11];
    const int*   idx     = (const int*)d_in[12];
    const int*   src     = (const int*)d_in[13];
    const int*   dst     = (const int*)d_in[14];
    const int*   typ     = (const int*)d_in[15];
    float* out = (float*)d_out;

    float* xsum_ptr; cudaGetSymbolAddress((void**)&xsum_ptr, g_xsum);

    // 0) init scratch (memset node is graph-capturable)
    cudaMemsetAsync(xsum_ptr, 0, (size_t)NSEG * DX * sizeof(float));
    init_kernel<<<1, 512>>>();

    // tiny precompute
    w2_kernel<<<32, 256>>>(Wq, Wk);
    vec_kernel<<<1, 512>>>(Wq, Wk, bq, bk);

    // 1) segment-sum scatter
    scatter_kernel<<<SC_NT / 256, 256>>>(tok_emb, mem, grp);

    // 4) fused gather-GEMM: wv
    {
        dim3 grid(DH / 128, QQ / 128);
        gemm_fused<<<grid, 256>>>(h_grp, idx, src, dst);
    }

    // 5) attention + rel head + metrics (block per group, dynamic smem)
    cudaFuncSetAttribute(attn_kernel, cudaFuncAttributeMaxDynamicSharedMemorySize, ATTN_SMEM_BYTES);
    attn_kernel<<<NN, 256, ATTN_SMEM_BYTES>>>(h_grp, Wrel, brel, idx, src, dst,
                                              pos2grp, msk, typ, out);

    // 6) finalize
    finalize_kernel<<<1, 512>>>(out);
}

// round 5
// speedup vs baseline: 1.1005x; 1.1005x over previous
#include <cuda_runtime.h>
#include <cuda_bf16.h>
#include <math.h>
#include <stdint.h>

// Problem constants
#define NN   512
#define LL   64
#define DH   256
#define DX   64
#define QQ   8192
#define NTYP 16
#define NMEM 262144
#define NSEG (NN*LL)        // 32768

// Scratch (device globals; no allocation allowed)
__device__ __align__(16) float g_xsum[NSEG * DX];       // 8 MB
__device__ __align__(16) float g_wv  [QQ * DH];         // 8 MB
__device__ __align__(16) float g_w2  [2 * DH * DH];     // 512x256 = WqT @ Wk
__device__ float g_u   [2 * DH];          // WqT @ bk
__device__ float g_b2  [DH];              // bq @ Wk
__device__ float g_cq;                    // bk . bq
__device__ int   g_em  [NN];
__device__ int   g_acc_cnt;

// ---------------------------------------------------------------------------
// Kernel 0: tiny init (xsum is zeroed by cudaMemsetAsync)
// ---------------------------------------------------------------------------
__global__ void init_kernel() {
    int tid = threadIdx.x;   // 512
    g_em[tid] = 0x7fffffff;
    if (tid == 0) g_acc_cnt = 0;
}

// ---------------------------------------------------------------------------
// Kernel 1: x_sum = segment_sum(tok_emb[mem], grp)  (MLP=4, v4 red)
// ---------------------------------------------------------------------------
#define SC_NT (NMEM * 16 / 4)   // 1,048,576 threads
__global__ __launch_bounds__(256)
void scatter_kernel(const float* __restrict__ tok_emb,
                    const int*   __restrict__ mem,
                    const int*   __restrict__ grp) {
    int t = blockIdx.x * 256 + threadIdx.x;
    int   gg[4], qd[4];
    float4 v[4];
    #pragma unroll
    for (int k = 0; k < 4; k++) {
        int task = t + k * SC_NT;
        int e = task >> 4;
        qd[k] = task & 15;
        int tok = __ldg(&mem[e]);
        gg[k]  = __ldg(&grp[e]);
        v[k] = __ldg(reinterpret_cast<const float4*>(tok_emb) + tok * 16 + qd[k]);
    }
    #pragma unroll
    for (int k = 0; k < 4; k++) {
        float* dst = &g_xsum[(size_t)gg[k] * DX + qd[k] * 4];
        asm volatile("red.global.add.v4.f32 [%0], {%1, %2, %3, %4};"
                     :: "l"(dst), "f"(v[k].x), "f"(v[k].y), "f"(v[k].z), "f"(v[k].w)
                     : "memory");
    }
}

// ---------------------------------------------------------------------------
// Kernel 2: W2[k,e] = sum_d Wq[d,k] * Wk[d,e]   (512 x 256, K=256)
// ---------------------------------------------------------------------------
__global__ __launch_bounds__(256)
void w2_kernel(const float* __restrict__ Wq, const float* __restrict__ Wk) {
    __shared__ float s_wq[DH][16];      // [d][kl]
    int tid = threadIdx.x;
    int k0 = blockIdx.x * 16;
    #pragma unroll
    for (int r = 0; r < 16; r++) {
        int fid = tid + r * 256;        // 0..4095
        int d = fid >> 4, kl = fid & 15;
        s_wq[d][kl] = __ldg(&Wq[(size_t)d * (2 * DH) + k0 + kl]);
    }
    __syncthreads();
    float acc[16] = {};
    int e = tid;
    #pragma unroll 4
    for (int d = 0; d < DH; d++) {
        float wkv = __ldg(&Wk[(size_t)d * DH + e]);
        #pragma unroll
        for (int kl = 0; kl < 16; kl++) acc[kl] += s_wq[d][kl] * wkv;
    }
    #pragma unroll
    for (int kl = 0; kl < 16; kl++)
        g_w2[(size_t)(k0 + kl) * DH + e] = acc[kl];
}

// ---------------------------------------------------------------------------
// Kernel 3: u[k] = Wq^T bk ; b2[e] = bq Wk ; cq = bk.bq
// ---------------------------------------------------------------------------
__global__ __launch_bounds__(512)
void vec_kernel(const float* __restrict__ Wq, const float* __restrict__ Wk,
                const float* __restrict__ bq, const float* __restrict__ bk) {
    int tid = threadIdx.x;
    float ua = 0.f;
    for (int d = 0; d < DH; d++) ua += __ldg(&bk[d]) * __ldg(&Wq[(size_t)d * (2 * DH) + tid]);
    g_u[tid] = ua;
    if (tid < DH) {
        float b2 = 0.f;
        for (int d = 0; d < DH; d++) b2 += __ldg(&bq[d]) * __ldg(&Wk[(size_t)d * DH + tid]);
        g_b2[tid] = b2;
    }
    if (tid == 0) {
        float c = 0.f;
        for (int d = 0; d < DH; d++) c += __ldg(&bk[d]) * __ldg(&bq[d]);
        g_cq = c;
    }
}

// ---------------------------------------------------------------------------
// Kernel 4: fused gather-GEMM: wv[q,e] = sum_k q_in[q,k]*W2[k,e] + b2[e]
// BM=BN=128, BK=16, 256 threads, 8x8 microtile, double-buffered.
// ---------------------------------------------------------------------------
__global__ __launch_bounds__(256)
void gemm_fused(const float* __restrict__ h_grp,
                const int* __restrict__ idx,
                const int* __restrict__ src,
                const int* __restrict__ dst) {
    __shared__ float As[2][16][128];
    __shared__ float Bs[2][16][128];
    __shared__ int   sOff[2][128];

    const int tid  = threadIdx.x;
    const int row0 = blockIdx.y * 128;
    const int col0 = blockIdx.x * 128;

    if (tid < 128) {
        int q = row0 + tid;
        int i = __ldg(&idx[q]);
        sOff[0][tid] = (i * LL + __ldg(&src[q])) * DH;
        sOff[1][tid] = (i * LL + __ldg(&dst[q])) * DH;
    }
    __syncthreads();

    const int am0 = tid >> 2,          akc0 = (tid & 3) * 4;
    const int am1 = (tid + 256) >> 2,  akc1 = (tid & 3) * 4;
    const int bk0 = tid >> 5,          bc0 = (tid & 31) * 4;
    const int bk1 = (tid + 256) >> 5,  bc1 = (tid & 31) * 4;

    float4 rA0, rA1, rB0, rB1;

    auto loadTile = [&](int t) {
        int k0 = t * 16;
        int half = k0 >> 8;
        int kb = k0 & 255;
        rA0 = *reinterpret_cast<const float4*>(h_grp + sOff[half][am0] + kb + akc0);
        rA1 = *reinterpret_cast<const float4*>(h_grp + sOff[half][am1] + kb + akc1);
        rB0 = *reinterpret_cast<const float4*>(&g_w2[(size_t)(k0 + bk0) * DH + col0 + bc0]);
        rB1 = *reinterpret_cast<const float4*>(&g_w2[(size_t)(k0 + bk1) * DH + col0 + bc1]);
    };
    auto storeTile = [&](int buf) {
        As[buf][akc0 + 0][am0] = rA0.x; As[buf][akc0 + 1][am0] = rA0.y;
        As[buf][akc0 + 2][am0] = rA0.z; As[buf][akc0 + 3][am0] = rA0.w;
        As[buf][akc1 + 0][am1] = rA1.x; As[buf][akc1 + 1][am1] = rA1.y;
        As[buf][akc1 + 2][am1] = rA1.z; As[buf][akc1 + 3][am1] = rA1.w;
        *reinterpret_cast<float4*>(&Bs[buf][bk0][bc0]) = rB0;
        *reinterpret_cast<float4*>(&Bs[buf][bk1][bc1]) = rB1;
    };

    loadTile(0);
    storeTile(0);
    __syncthreads();

    float acc[8][8] = {};
    const int ty8 = (tid >> 4) * 8;
    const int tx8 = (tid & 15) * 8;

    for (int t = 0; t < 32; t++) {
        int buf = t & 1;
        if (t < 31) loadTile(t + 1);
        #pragma unroll
        for (int k = 0; k < 16; k++) {
            float4 a0 = *reinterpret_cast<const float4*>(&As[buf][k][ty8]);
            float4 a1 = *reinterpret_cast<const float4*>(&As[buf][k][ty8 + 4]);
            float4 b0 = *reinterpret_cast<const float4*>(&Bs[buf][k][tx8]);
            float4 b1 = *reinterpret_cast<const float4*>(&Bs[buf][k][tx8 + 4]);
            float av[8] = {a0.x, a0.y, a0.z, a0.w, a1.x, a1.y, a1.z, a1.w};
            float bv[8] = {b0.x, b0.y, b0.z, b0.w, b1.x, b1.y, b1.z, b1.w};
            #pragma unroll
            for (int i = 0; i < 8; i++)
                #pragma unroll
                for (int j = 0; j < 8; j++)
                    acc[i][j] += av[i] * bv[j];
        }
        if (t < 31) {
            storeTile(buf ^ 1);
            __syncthreads();
        }
    }

    float bb[8];
    #pragma unroll
    for (int j = 0; j < 8; j++) bb[j] = g_b2[col0 + tx8 + j];
    #pragma unroll
    for (int i = 0; i < 8; i++) {
        int q = row0 + ty8 + i;
        float* cr = g_wv + (size_t)q * DH + col0 + tx8;
        float4 o0 = {acc[i][0] + bb[0], acc[i][1] + bb[1], acc[i][2] + bb[2], acc[i][3] + bb[3]};
        float4 o1 = {acc[i][4] + bb[4], acc[i][5] + bb[5], acc[i][6] + bb[6], acc[i][7] + bb[7]};
        *reinterpret_cast<float4*>(cr)     = o0;
        *reinterpret_cast<float4*>(cr + 4) = o1;
    }
}

// ---------------------------------------------------------------------------
// Kernel 5: block-per-group, WARP-PER-QUERY attention + rel head + metrics.
// No block-wide syncs in the query loop. h staged transposed: scores land
// per-lane with zero reductions.
// ---------------------------------------------------------------------------
__device__ __forceinline__ int lbound(const int* __restrict__ a, int n, int key) {
    int lo = 0, hi = n;
    while (lo < hi) { int m = (lo + hi) >> 1; if (__ldg(&a[m]) < key) lo = m + 1; else hi = m; }
    return lo;
}

#define ATTN_SMEM_FLOATS (16384 + 4096 + 2048 + 512 + 64 + 64 + 16)
#define ATTN_SMEM_BYTES  (ATTN_SMEM_FLOATS * 4)

__global__ __launch_bounds__(256)
void attn_kernel(const float* __restrict__ h_grp,
                 const float* __restrict__ Wrel,
                 const float* __restrict__ brel,
                 const int*   __restrict__ idx,
                 const int*   __restrict__ src,
                 const int*   __restrict__ dst,
                 const int*   __restrict__ pos2grp,
                 const int*   __restrict__ msk,
                 const int*   __restrict__ typ,
                 float* __restrict__ out_logit) {
    extern __shared__ float sm[];
    float* s_ht  = sm;                    // 16384 : transposed h, s_ht[e*64 + l]
    float* s_xg  = s_ht  + 16384;         // 4096  : x_grp rows [l][64]
    float* s_wvb = s_xg  + 4096;          // 2048  : per-warp wv (8*256)
    float* s_ab  = s_wvb + 2048;          // 512   : per-warp a (8*64)
    float* s_msk = s_ab  + 512;           // 64
    int*   s_g   = (int*)(s_msk + 64);    // 64
    int*   s_acc = s_g + 64;              // 8
    int*   s_em  = s_acc + 8;             // 8

    const int n    = blockIdx.x;
    const int tid  = threadIdx.x;     // 256
    const int lane = tid & 31;
    const int w    = tid >> 5;        // 8 warps

    const int lo = lbound(idx, QQ, n);
    const int hi = lbound(idx, QQ, n + 1);
    if (lo >= hi) return;             // uniform: whole block exits

    // stage h transposed. thread: l = v & 63 (lane-distinct -> conflict-free STS)
    {
        const float4* hb4 = reinterpret_cast<const float4*>(h_grp + (size_t)n * LL * DH);
        #pragma unroll
        for (int k = 0; k < 16; k++) {
            int v = tid + k * 256;
            int l = v & 63, e4 = v >> 6;
            float4 hv = __ldg(hb4 + l * 64 + e4);
            int e = e4 * 4;
            s_ht[(e + 0) * 64 + l] = hv.x;
            s_ht[(e + 1) * 64 + l] = hv.y;
            s_ht[(e + 2) * 64 + l] = hv.z;
            s_ht[(e + 3) * 64 + l] = hv.w;
        }
    }
    if (tid < LL) {
        s_g[tid]   = __ldg(&pos2grp[n * LL + tid]);
        s_msk[tid] = (__ldg(&msk[n * LL + tid]) == 0) ? -INFINITY : 0.f;
    }
    __syncthreads();

    // gather x_grp rows (64x64 floats)
    {
        float4* sx4 = reinterpret_cast<float4*>(s_xg);
        const float4* xs4 = reinterpret_cast<const float4*>(g_xsum);
        #pragma unroll
        for (int k = 0; k < 4; k++) {
            int v = tid + k * 256;
            int row = v >> 4, c4 = v & 15;
            sx4[v] = __ldg(xs4 + (size_t)s_g[row] * 16 + c4);
        }
    }
    __syncthreads();

    int accW = 0, emW = 1;
    const float2* ht2 = reinterpret_cast<const float2*>(s_ht);
    float* wvp = s_wvb + w * 256;
    float* abp = s_ab  + w * 64;
    const float mk0 = s_msk[2 * lane];
    const float mk1 = s_msk[2 * lane + 1];

    for (int q = lo + w; q < hi; q += 8) {
        const int sp = __ldg(&src[q]);
        const int dp = __ldg(&dst[q]);

        // stage this query's wv into per-warp smem
        const float4* wv4 = reinterpret_cast<const float4*>(g_wv + (size_t)q * DH);
        reinterpret_cast<float4*>(wvp)[lane]      = __ldg(wv4 + lane);
        reinterpret_cast<float4*>(wvp)[32 + lane] = __ldg(wv4 + 32 + lane);
        __syncwarp();

        // q_in registers + c = q_in.u + cq   (8 chunks of 32 -> 256 per row)
        const float* hs = h_grp + ((size_t)n * LL + sp) * DH;
        const float* hd = h_grp + ((size_t)n * LL + dp) * DH;
        float qs[8], qd[8];
        float cp = 0.f;
        #pragma unroll
        for (int k = 0; k < 8; k++) {
            int e = lane + 32 * k;
            qs[k] = __ldg(hs + e);
            qd[k] = __ldg(hd + e);
            cp += qs[k] * __ldg(&g_u[e]) + qd[k] * __ldg(&g_u[DH + e]);
        }
        #pragma unroll
        for (int o = 16; o > 0; o >>= 1) cp += __shfl_xor_sync(0xffffffffu, cp, o);
        const float c = cp + g_cq;

        // scores for rows 2*lane, 2*lane+1 (no reductions)
        float p0 = 0.f, p1 = 0.f;
        #pragma unroll 8
        for (int e = 0; e < DH; e++) {
            float wv_ = wvp[e];                 // broadcast
            float2 hv = ht2[e * 32 + lane];     // conflict-free
            p0 += hv.x * wv_;
            p1 += hv.y * wv_;
        }
        float v0 = (p0 + c) * 0.0625f + mk0;
        float v1 = (p1 + c) * 0.0625f + mk1;

        // warp softmax over 64
        float mmx = fmaxf(v0, v1);
        #pragma unroll
        for (int o = 16; o > 0; o >>= 1) mmx = fmaxf(mmx, __shfl_xor_sync(0xffffffffu, mmx, o));
        float e0 = __expf(v0 - mmx), e1 = __expf(v1 - mmx);
        float ssum = e0 + e1;
        #pragma unroll
        for (int o = 16; o > 0; o >>= 1) ssum += __shfl_xor_sync(0xffffffffu, ssum, o);
        float inv = 1.f / ssum;
        reinterpret_cast<float2*>(abp)[lane] = make_float2(e0 * inv, e1 * inv);
        __syncwarp();

        // attn[j] for j = lane, lane+32
        float at0 = 0.f, at1 = 0.f;
        #pragma unroll
        for (int l = 0; l < LL; l++) {
            float al = abp[l];                  // broadcast
            at0 += al * s_xg[l * DX + lane];
            at1 += al * s_xg[l * DX + 32 + lane];
        }

        // rel head: 16 logits, warp-parallel dots over 576
        int eqCnt = 0, eqAll = 1;
        #pragma unroll 4
        for (int t = 0; t < NTYP; t++) {
            const float* wr = Wrel + (size_t)t * (2 * DH + DX);
            float p = at0 * __ldg(wr + 2 * DH + lane) + at1 * __ldg(wr + 2 * DH + 32 + lane);
            #pragma unroll
            for (int k = 0; k < 8; k++) {
                int e = lane + 32 * k;
                p += qs[k] * __ldg(wr + e) + qd[k] * __ldg(wr + DH + e);
            }
            #pragma unroll
            for (int o = 16; o > 0; o >>= 1) p += __shfl_xor_sync(0xffffffffu, p, o);
            if (lane == 0) {
                p += __ldg(&brel[t]);
                out_logit[(size_t)q * NTYP + t] = p;
                int gt = (p > 0.f) ? 1 : 0;
                int ty = (__ldg(&typ[q * NTYP + t]) > 0) ? 1 : 0;
                int eq = (gt == ty) ? 1 : 0;
                eqCnt += eq; eqAll &= eq;
            }
        }
        if (lane == 0) { accW += eqCnt; emW &= eqAll; }
    }

    if (lane == 0) { s_acc[w] = accW; s_em[w] = emW; }
    __syncthreads();
    if (tid == 0) {
        int a = 0, e = 1;
        #pragma unroll
        for (int r = 0; r < 8; r++) { a += s_acc[r]; e &= s_em[r]; }
        atomicAdd(&g_acc_cnt, a);
        g_em[n] = e;
    }
}

// ---------------------------------------------------------------------------
// Kernel 6: finalize scalars. out layout: [logit(131072), acc, emr, em(512)]
// ---------------------------------------------------------------------------
__global__ __launch_bounds__(512)
void finalize_kernel(float* __restrict__ out) {
    __shared__ float s_red[16];
    int tid = threadIdx.x;            // 512
    int lane = tid & 31, w = tid >> 5;
    float e = (float)g_em[tid];
    out[QQ * NTYP + 2 + tid] = e;
    float p = e;
    #pragma unroll
    for (int o = 16; o > 0; o >>= 1) p += __shfl_xor_sync(0xffffffffu, p, o);
    if (lane == 0) s_red[w] = p;
    __syncthreads();
    if (tid == 0) {
        float sum = 0.f;
        #pragma unroll
        for (int r = 0; r < 16; r++) sum += s_red[r];
        out[QQ * NTYP + 0] = (float)g_acc_cnt / (float)(QQ * NTYP);
        out[QQ * NTYP + 1] = sum / (float)NN;
    }
}

// ---------------------------------------------------------------------------
extern "C" void kernel_launch(void* const* d_in, const int* in_sizes, int n_in,
                              void* d_out, int out_size) {
    const float* h_grp   = (const float*)d_in[0];
    const float* tok_emb = (const float*)d_in[1];
    const float* Wq      = (const float*)d_in[2];
    const float* bq      = (const float*)d_in[3];
    const float* Wk      = (const float*)d_in[4];
    const float* bk      = (const float*)d_in[5];
    const float* Wrel    = (const float*)d_in[6];
    const float* brel    = (const float*)d_in[7];
    const int*   mem     = (const int*)d_in[8];
    const int*   grp     = (const int*)d_in[9];
    const int*   pos2grp = (const int*)d_in[10];
    const int*   msk     = (const int*)d_in[11];
    const int*   idx     = (const int*)d_in[12];
    const int*   src     = (const int*)d_in[13];
    const int*   dst     = (const int*)d_in[14];
    const int*   typ     = (const int*)d_in[15];
    float* out = (float*)d_out;

    float* xsum_ptr; cudaGetSymbolAddress((void**)&xsum_ptr, g_xsum);

    // 0) init scratch (memset node is graph-capturable)
    cudaMemsetAsync(xsum_ptr, 0, (size_t)NSEG * DX * sizeof(float));
    init_kernel<<<1, 512>>>();

    // tiny precompute
    w2_kernel<<<32, 256>>>(Wq, Wk);
    vec_kernel<<<1, 512>>>(Wq, Wk, bq, bk);

    // 1) segment-sum scatter
    scatter_kernel<<<SC_NT / 256, 256>>>(tok_emb, mem, grp);

    // 4) fused gather-GEMM: wv
    {
        dim3 grid(DH / 128, QQ / 128);
        gemm_fused<<<grid, 256>>>(h_grp, idx, src, dst);
    }

    // 5) attention + rel head + metrics (block per group, warp per query)
    cudaFuncSetAttribute(attn_kernel, cudaFuncAttributeMaxDynamicSharedMemorySize, ATTN_SMEM_BYTES);
    attn_kernel<<<NN, 256, ATTN_SMEM_BYTES>>>(h_grp, Wrel, brel, idx, src, dst,
                                              pos2grp, msk, typ, out);

    // 6) finalize
    finalize_kernel<<<1, 512>>>(out);
}

// round 6
// speedup vs baseline: 1.2943x; 1.1761x over previous
#include <cuda_runtime.h>
#include <cuda_bf16.h>
#include <math.h>
#include <stdint.h>

// Problem constants
#define NN   512
#define LL   64
#define DH   256
#define DX   64
#define QQ   8192
#define NTYP 16
#define NMEM 262144
#define NSEG (NN*LL)        // 32768

// Scratch (device globals; no allocation allowed)
__device__ __align__(16) float g_xsum[NSEG * DX];       // 8 MB
__device__ __align__(16) float g_wv  [QQ * DH];         // 8 MB
__device__ __align__(16) float g_w2  [2 * DH * DH];     // 512x256 = WqT @ Wk
__device__ float g_u   [2 * DH];          // WqT @ bk
__device__ float g_b2  [DH];              // bq @ Wk
__device__ float g_cq;                    // bk . bq
__device__ int   g_em  [NN];
__device__ int   g_acc_cnt;

// ---------------------------------------------------------------------------
// Kernel 1: W2 = WqT @ Wk (blocks 0-31) + vec/init work (block 32)
// ---------------------------------------------------------------------------
__global__ __launch_bounds__(256)
void w2v_kernel(const float* __restrict__ Wq, const float* __restrict__ Wk,
                const float* __restrict__ bq, const float* __restrict__ bk) {
    int tid = threadIdx.x;
    if (blockIdx.x == 32) {
        // u[k] = Wq^T bk (512), b2 = bq @ Wk (256), cq = bk.bq, init em/acc
        #pragma unroll
        for (int rep = 0; rep < 2; rep++) {
            int k = tid + rep * 256;
            float ua = 0.f;
            for (int d = 0; d < DH; d++)
                ua += __ldg(&bk[d]) * __ldg(&Wq[(size_t)d * (2 * DH) + k]);
            g_u[k] = ua;
        }
        float b2 = 0.f;
        for (int d = 0; d < DH; d++)
            b2 += __ldg(&bq[d]) * __ldg(&Wk[(size_t)d * DH + tid]);
        g_b2[tid] = b2;
        g_em[tid] = 0x7fffffff;
        g_em[tid + 256] = 0x7fffffff;
        if (tid == 0) {
            float c = 0.f;
            for (int d = 0; d < DH; d++) c += __ldg(&bk[d]) * __ldg(&bq[d]);
            g_cq = c;
            g_acc_cnt = 0;
        }
        return;
    }
    __shared__ float s_wq[DH][16];      // [d][kl]
    int k0 = blockIdx.x * 16;
    #pragma unroll
    for (int r = 0; r < 16; r++) {
        int fid = tid + r * 256;        // 0..4095
        int d = fid >> 4, kl = fid & 15;
        s_wq[d][kl] = __ldg(&Wq[(size_t)d * (2 * DH) + k0 + kl]);
    }
    __syncthreads();
    float acc[16] = {};
    int e = tid;
    #pragma unroll 4
    for (int d = 0; d < DH; d++) {
        float wkv = __ldg(&Wk[(size_t)d * DH + e]);
        #pragma unroll
        for (int kl = 0; kl < 16; kl++) acc[kl] += s_wq[d][kl] * wkv;
    }
    #pragma unroll
    for (int kl = 0; kl < 16; kl++)
        g_w2[(size_t)(k0 + kl) * DH + e] = acc[kl];
}

// ---------------------------------------------------------------------------
// Kernel 2: x_sum = segment_sum(tok_emb[mem], grp)  (MLP=4, v4 red)
// ---------------------------------------------------------------------------
#define SC_NT (NMEM * 16 / 4)   // 1,048,576 threads
__global__ __launch_bounds__(256)
void scatter_kernel(const float* __restrict__ tok_emb,
                    const int*   __restrict__ mem,
                    const int*   __restrict__ grp) {
    int t = blockIdx.x * 256 + threadIdx.x;
    int   gg[4], qd[4];
    float4 v[4];
    #pragma unroll
    for (int k = 0; k < 4; k++) {
        int task = t + k * SC_NT;
        int e = task >> 4;
        qd[k] = task & 15;
        int tok = __ldg(&mem[e]);
        gg[k]  = __ldg(&grp[e]);
        v[k] = __ldg(reinterpret_cast<const float4*>(tok_emb) + tok * 16 + qd[k]);
    }
    #pragma unroll
    for (int k = 0; k < 4; k++) {
        float* dst = &g_xsum[(size_t)gg[k] * DX + qd[k] * 4];
        asm volatile("red.global.add.v4.f32 [%0], {%1, %2, %3, %4};"
                     :: "l"(dst), "f"(v[k].x), "f"(v[k].y), "f"(v[k].z), "f"(v[k].w)
                     : "memory");
    }
}

// ---------------------------------------------------------------------------
// Kernel 3: TF32 tensor-core gather-GEMM: wv = q_in @ W2 + b2
// BM=128, BN=128, BK=32, 256 threads (8 warps, 2x4), warp tile 64x32,
// mma.sync m16n8k8 tf32, double-buffered smem, conflict-free padding.
// ---------------------------------------------------------------------------
#define AS_STRIDE 36    // bank = 4*(lane>>2) + (lane&3) = lane -> conflict-free
#define BS_STRIDE 136   // bank = 8*(lane&3) + (lane>>2) -> conflict-free
#define GEMM_SMEM_FLOATS (2 * 128 * AS_STRIDE + 2 * 32 * BS_STRIDE + 2 * 128)
#define GEMM_SMEM_BYTES  (GEMM_SMEM_FLOATS * 4)

__device__ __forceinline__ void mma_tf32(float* c, const uint32_t* a, const uint32_t* b) {
    asm volatile(
        "mma.sync.aligned.m16n8k8.row.col.f32.tf32.tf32.f32 "
        "{%0,%1,%2,%3}, {%4,%5,%6,%7}, {%8,%9}, {%0,%1,%2,%3};"
        : "+f"(c[0]), "+f"(c[1]), "+f"(c[2]), "+f"(c[3])
        : "r"(a[0]), "r"(a[1]), "r"(a[2]), "r"(a[3]), "r"(b[0]), "r"(b[1]));
}

__global__ __launch_bounds__(256)
void gemm_tf32(const float* __restrict__ h_grp,
               const int* __restrict__ idx,
               const int* __restrict__ src,
               const int* __restrict__ dst) {
    extern __shared__ float dsm[];
    float* As = dsm;                                  // [2][128][AS_STRIDE]
    float* Bs = dsm + 2 * 128 * AS_STRIDE;            // [2][32][BS_STRIDE]
    int*  sOff = (int*)(Bs + 2 * 32 * BS_STRIDE);     // [2][128]

    const int tid  = threadIdx.x;
    const int lane = tid & 31;
    const int w    = tid >> 5;
    const int wm   = (w >> 2) * 64;    // warp M offset (0/64)
    const int wn   = (w & 3) * 32;     // warp N offset (0/32/64/96)
    const int row0 = blockIdx.y * 128;
    const int col0 = blockIdx.x * 128;

    if (tid < 128) {
        int q = row0 + tid;
        int i = __ldg(&idx[q]);
        sOff[tid]       = (i * LL + __ldg(&src[q])) * DH;
        sOff[128 + tid] = (i * LL + __ldg(&dst[q])) * DH;
    }
    __syncthreads();

    // staging thread mapping
    const int amr = tid >> 3;           // A: base row, +32 per j (4 float4/thread)
    const int ac4 = (tid & 7) * 4;      // A: col within 32
    const int bkr = tid >> 5;           // B: base k, +8 per j
    const int bn4 = (tid & 31) * 4;     // B: col within 128

    float4 rA[4], rB[4];
    auto ldgChunk = [&](int ch) {
        int kb = ch * 32;
        const int* off = sOff + ((kb >> 8) << 7);   // src/dst half
        int kbl = kb & 255;
        #pragma unroll
        for (int j = 0; j < 4; j++)
            rA[j] = *reinterpret_cast<const float4*>(h_grp + off[amr + 32 * j] + kbl + ac4);
        #pragma unroll
        for (int j = 0; j < 4; j++)
            rB[j] = *reinterpret_cast<const float4*>(&g_w2[(size_t)(kb + bkr + 8 * j) * DH + col0 + bn4]);
    };
    auto stsChunk = [&](int buf) {
        float* a = As + buf * 128 * AS_STRIDE;
        float* b = Bs + buf * 32 * BS_STRIDE;
        #pragma unroll
        for (int j = 0; j < 4; j++)
            *reinterpret_cast<float4*>(a + (amr + 32 * j) * AS_STRIDE + ac4) = rA[j];
        #pragma unroll
        for (int j = 0; j < 4; j++)
            *reinterpret_cast<float4*>(b + (bkr + 8 * j) * BS_STRIDE + bn4) = rB[j];
    };

    float acc[4][4][4] = {};

    ldgChunk(0); stsChunk(0); __syncthreads();

    for (int t = 0; t < 16; t++) {
        int buf = t & 1;
        if (t < 15) ldgChunk(t + 1);
        const float* a = As + buf * 128 * AS_STRIDE;
        const float* b = Bs + buf * 32 * BS_STRIDE;
        const int ar = wm + (lane >> 2);
        const int bn = wn + (lane >> 2);
        #pragma unroll
        for (int ks = 0; ks < 4; ks++) {
            int kc = ks * 8 + (lane & 3);
            uint32_t af[4][4], bf[4][2];
            #pragma unroll
            for (int mt = 0; mt < 4; mt++) {
                const float* ap = a + (ar + mt * 16) * AS_STRIDE + kc;
                af[mt][0] = __float_as_uint(ap[0]);
                af[mt][1] = __float_as_uint(ap[8 * AS_STRIDE]);
                af[mt][2] = __float_as_uint(ap[4]);
                af[mt][3] = __float_as_uint(ap[8 * AS_STRIDE + 4]);
            }
            #pragma unroll
            for (int nt = 0; nt < 4; nt++) {
                const float* bp = b + kc * BS_STRIDE + bn + nt * 8;
                bf[nt][0] = __float_as_uint(bp[0]);
                bf[nt][1] = __float_as_uint(bp[4 * BS_STRIDE]);
            }
            #pragma unroll
            for (int mt = 0; mt < 4; mt++)
                #pragma unroll
                for (int nt = 0; nt < 4; nt++)
                    mma_tf32(acc[mt][nt], af[mt], bf[nt]);
        }
        if (t < 15) {
            stsChunk(buf ^ 1);       // writes other buffer: safe vs concurrent reads of buf
            __syncthreads();
        }
    }

    // epilogue: add b2, store fp32
    #pragma unroll
    for (int mt = 0; mt < 4; mt++) {
        int r = row0 + wm + mt * 16 + (lane >> 2);
        #pragma unroll
        for (int nt = 0; nt < 4; nt++) {
            int cb = col0 + wn + nt * 8 + (lane & 3) * 2;
            float b0 = __ldg(&g_b2[cb]);
            float b1 = __ldg(&g_b2[cb + 1]);
            *reinterpret_cast<float2*>(&g_wv[(size_t)r * DH + cb]) =
                make_float2(acc[mt][nt][0] + b0, acc[mt][nt][1] + b1);
            *reinterpret_cast<float2*>(&g_wv[(size_t)(r + 8) * DH + cb]) =
                make_float2(acc[mt][nt][2] + b0, acc[mt][nt][3] + b1);
        }
    }
}

// ---------------------------------------------------------------------------
// Kernel 4: block-per-group, WARP-PER-QUERY attention + rel head + metrics.
// ---------------------------------------------------------------------------
__device__ __forceinline__ int lbound(const int* __restrict__ a, int n, int key) {
    int lo = 0, hi = n;
    while (lo < hi) { int m = (lo + hi) >> 1; if (__ldg(&a[m]) < key) lo = m + 1; else hi = m; }
    return lo;
}

#define ATTN_SMEM_FLOATS (16384 + 4096 + 2048 + 512 + 64 + 64 + 16)
#define ATTN_SMEM_BYTES  (ATTN_SMEM_FLOATS * 4)

__global__ __launch_bounds__(256)
void attn_kernel(const float* __restrict__ h_grp,
                 const float* __restrict__ Wrel,
                 const float* __restrict__ brel,
                 const int*   __restrict__ idx,
                 const int*   __restrict__ src,
                 const int*   __restrict__ dst,
                 const int*   __restrict__ pos2grp,
                 const int*   __restrict__ msk,
                 const int*   __restrict__ typ,
                 float* __restrict__ out_logit) {
    extern __shared__ float sm[];
    float* s_ht  = sm;                    // 16384 : transposed h, s_ht[e*64 + l]
    float* s_xg  = s_ht  + 16384;         // 4096  : x_grp rows [l][64]
    float* s_wvb = s_xg  + 4096;          // 2048  : per-warp wv (8*256)
    float* s_ab  = s_wvb + 2048;          // 512   : per-warp a (8*64)
    float* s_msk = s_ab  + 512;           // 64
    int*   s_g   = (int*)(s_msk + 64);    // 64
    int*   s_acc = s_g + 64;              // 8
    int*   s_em  = s_acc + 8;             // 8

    const int n    = blockIdx.x;
    const int tid  = threadIdx.x;     // 256
    const int lane = tid & 31;
    const int w    = tid >> 5;        // 8 warps

    const int lo = lbound(idx, QQ, n);
    const int hi = lbound(idx, QQ, n + 1);
    if (lo >= hi) return;             // uniform: whole block exits

    // stage h transposed (conflict-free STS)
    {
        const float4* hb4 = reinterpret_cast<const float4*>(h_grp + (size_t)n * LL * DH);
        #pragma unroll
        for (int k = 0; k < 16; k++) {
            int v = tid + k * 256;
            int l = v & 63, e4 = v >> 6;
            float4 hv = __ldg(hb4 + l * 64 + e4);
            int e = e4 * 4;
            s_ht[(e + 0) * 64 + l] = hv.x;
            s_ht[(e + 1) * 64 + l] = hv.y;
            s_ht[(e + 2) * 64 + l] = hv.z;
            s_ht[(e + 3) * 64 + l] = hv.w;
        }
    }
    if (tid < LL) {
        s_g[tid]   = __ldg(&pos2grp[n * LL + tid]);
        s_msk[tid] = (__ldg(&msk[n * LL + tid]) == 0) ? -INFINITY : 0.f;
    }
    __syncthreads();

    // gather x_grp rows (64x64 floats)
    {
        float4* sx4 = reinterpret_cast<float4*>(s_xg);
        const float4* xs4 = reinterpret_cast<const float4*>(g_xsum);
        #pragma unroll
        for (int k = 0; k < 4; k++) {
            int v = tid + k * 256;
            int row = v >> 4, c4 = v & 15;
            sx4[v] = __ldg(xs4 + (size_t)s_g[row] * 16 + c4);
        }
    }
    __syncthreads();

    int accW = 0, emW = 1;
    const float2* ht2 = reinterpret_cast<const float2*>(s_ht);
    float* wvp = s_wvb + w * 256;
    float* abp = s_ab  + w * 64;
    const float mk0 = s_msk[2 * lane];
    const float mk1 = s_msk[2 * lane + 1];

    for (int q = lo + w; q < hi; q += 8) {
        const int sp = __ldg(&src[q]);
        const int dp = __ldg(&dst[q]);

        const float4* wv4 = reinterpret_cast<const float4*>(g_wv + (size_t)q * DH);
        reinterpret_cast<float4*>(wvp)[lane]      = __ldg(wv4 + lane);
        reinterpret_cast<float4*>(wvp)[32 + lane] = __ldg(wv4 + 32 + lane);
        __syncwarp();

        // q_in registers + c = q_in.u + cq   (8 chunks of 32 -> 256 per row)
        const float* hs = h_grp + ((size_t)n * LL + sp) * DH;
        const float* hd = h_grp + ((size_t)n * LL + dp) * DH;
        float qs[8], qd[8];
        float cp = 0.f;
        #pragma unroll
        for (int k = 0; k < 8; k++) {
            int e = lane + 32 * k;
            qs[k] = __ldg(hs + e);
            qd[k] = __ldg(hd + e);
            cp += qs[k] * __ldg(&g_u[e]) + qd[k] * __ldg(&g_u[DH + e]);
        }
        #pragma unroll
        for (int o = 16; o > 0; o >>= 1) cp += __shfl_xor_sync(0xffffffffu, cp, o);
        const float c = cp + g_cq;

        // scores for rows 2*lane, 2*lane+1 (no reductions)
        float p0 = 0.f, p1 = 0.f;
        #pragma unroll 8
        for (int e = 0; e < DH; e++) {
            float wv_ = wvp[e];                 // broadcast
            float2 hv = ht2[e * 32 + lane];     // conflict-free
            p0 += hv.x * wv_;
            p1 += hv.y * wv_;
        }
        float v0 = (p0 + c) * 0.0625f + mk0;
        float v1 = (p1 + c) * 0.0625f + mk1;

        // warp softmax over 64
        float mmx = fmaxf(v0, v1);
        #pragma unroll
        for (int o = 16; o > 0; o >>= 1) mmx = fmaxf(mmx, __shfl_xor_sync(0xffffffffu, mmx, o));
        float e0 = __expf(v0 - mmx), e1 = __expf(v1 - mmx);
        float ssum = e0 + e1;
        #pragma unroll
        for (int o = 16; o > 0; o >>= 1) ssum += __shfl_xor_sync(0xffffffffu, ssum, o);
        float inv = 1.f / ssum;
        reinterpret_cast<float2*>(abp)[lane] = make_float2(e0 * inv, e1 * inv);
        __syncwarp();

        // attn[j] for j = lane, lane+32
        float at0 = 0.f, at1 = 0.f;
        #pragma unroll
        for (int l = 0; l < LL; l++) {
            float al = abp[l];                  // broadcast
            at0 += al * s_xg[l * DX + lane];
            at1 += al * s_xg[l * DX + 32 + lane];
        }

        // rel head: 16 logits, warp-parallel dots over 576
        int eqCnt = 0, eqAll = 1;
        #pragma unroll 4
        for (int t = 0; t < NTYP; t++) {
            const float* wr = Wrel + (size_t)t * (2 * DH + DX);
            float p = at0 * __ldg(wr + 2 * DH + lane) + at1 * __ldg(wr + 2 * DH + 32 + lane);
            #pragma unroll
            for (int k = 0; k < 8; k++) {
                int e = lane + 32 * k;
                p += qs[k] * __ldg(wr + e) + qd[k] * __ldg(wr + DH + e);
            }
            #pragma unroll
            for (int o = 16; o > 0; o >>= 1) p += __shfl_xor_sync(0xffffffffu, p, o);
            if (lane == 0) {
                p += __ldg(&brel[t]);
                out_logit[(size_t)q * NTYP + t] = p;
                int gt = (p > 0.f) ? 1 : 0;
                int ty = (__ldg(&typ[q * NTYP + t]) > 0) ? 1 : 0;
                int eq = (gt == ty) ? 1 : 0;
                eqCnt += eq; eqAll &= eq;
            }
        }
        if (lane == 0) { accW += eqCnt; emW &= eqAll; }
    }

    if (lane == 0) { s_acc[w] = accW; s_em[w] = emW; }
    __syncthreads();
    if (tid == 0) {
        int a = 0, e = 1;
        #pragma unroll
        for (int r = 0; r < 8; r++) { a += s_acc[r]; e &= s_em[r]; }
        atomicAdd(&g_acc_cnt, a);
        g_em[n] = e;
    }
}

// ---------------------------------------------------------------------------
// Kernel 5: finalize scalars. out layout: [logit(131072), acc, emr, em(512)]
// ---------------------------------------------------------------------------
__global__ __launch_bounds__(512)
void finalize_kernel(float* __restrict__ out) {
    __shared__ float s_red[16];
    int tid = threadIdx.x;            // 512
    int lane = tid & 31, w = tid >> 5;
    float e = (float)g_em[tid];
    out[QQ * NTYP + 2 + tid] = e;
    float p = e;
    #pragma unroll
    for (int o = 16; o > 0; o >>= 1) p += __shfl_xor_sync(0xffffffffu, p, o);
    if (lane == 0) s_red[w] = p;
    __syncthreads();
    if (tid == 0) {
        float sum = 0.f;
        #pragma unroll
        for (int r = 0; r < 16; r++) sum += s_red[r];
        out[QQ * NTYP + 0] = (float)g_acc_cnt / (float)(QQ * NTYP);
        out[QQ * NTYP + 1] = sum / (float)NN;
    }
}

// ---------------------------------------------------------------------------
extern "C" void kernel_launch(void* const* d_in, const int* in_sizes, int n_in,
                              void* d_out, int out_size) {
    const float* h_grp   = (const float*)d_in[0];
    const float* tok_emb = (const float*)d_in[1];
    const float* Wq      = (const float*)d_in[2];
    const float* bq      = (const float*)d_in[3];
    const float* Wk      = (const float*)d_in[4];
    const float* bk      = (const float*)d_in[5];
    const float* Wrel    = (const float*)d_in[6];
    const float* brel    = (const float*)d_in[7];
    const int*   mem     = (const int*)d_in[8];
    const int*   grp     = (const int*)d_in[9];
    const int*   pos2grp = (const int*)d_in[10];
    const int*   msk     = (const int*)d_in[11];
    const int*   idx     = (const int*)d_in[12];
    const int*   src     = (const int*)d_in[13];
    const int*   dst     = (const int*)d_in[14];
    const int*   typ     = (const int*)d_in[15];
    float* out = (float*)d_out;

    float* xsum_ptr; cudaGetSymbolAddress((void**)&xsum_ptr, g_xsum);

    // memset node (not a kernel launch)
    cudaMemsetAsync(xsum_ptr, 0, (size_t)NSEG * DX * sizeof(float));

    // kernel #1: W2 + vec + init
    w2v_kernel<<<33, 256>>>(Wq, Wk, bq, bk);

    // kernel #2: segment-sum scatter
    scatter_kernel<<<SC_NT / 256, 256>>>(tok_emb, mem, grp);

    // kernel #3: TF32 tensor-core gather-GEMM
    {
        cudaFuncSetAttribute(gemm_tf32, cudaFuncAttributeMaxDynamicSharedMemorySize, GEMM_SMEM_BYTES);
        dim3 grid(DH / 128, QQ / 128);
        gemm_tf32<<<grid, 256, GEMM_SMEM_BYTES>>>(h_grp, idx, src, dst);
    }

    // kernel #4 (ncu-profiled slot): attention + rel head + metrics
    cudaFuncSetAttribute(attn_kernel, cudaFuncAttributeMaxDynamicSharedMemorySize, ATTN_SMEM_BYTES);
    attn_kernel<<<NN, 256, ATTN_SMEM_BYTES>>>(h_grp, Wrel, brel, idx, src, dst,
                                              pos2grp, msk, typ, out);

    // kernel #5: finalize
    finalize_kernel<<<1, 512>>>(out);
}

// round 7
// speedup vs baseline: 1.6582x; 1.2811x over previous
#include <cuda_runtime.h>
#include <cuda_bf16.h>
#include <math.h>
#include <stdint.h>

// Problem constants
#define NN   512
#define LL   64
#define DH   256
#define DX   64
#define QQ   8192
#define NTYP 16
#define NMEM 262144
#define NSEG (NN*LL)        // 32768

// Scratch (device globals; no allocation allowed)
__device__ __align__(16) float g_xsum[NSEG * DX];       // 8 MB
__device__ __align__(16) float g_wv  [QQ * DH];         // 8 MB
__device__ __align__(16) float g_w2  [2 * DH * DH];     // 512x256 = WqT @ Wk
__device__ __align__(16) float g_y   [NSEG * NTYP];     // 2 MB : x_sum @ Wrel_x^T
__device__ __align__(16) float g_l0  [QQ * 32];         // 1 MB : q_in @ [Wrel_q^T | u | 0]
__device__ __align__(16) float g_bl0 [2 * DH * 32];     // 512x32 B for l0 GEMM
__device__ float g_u   [2 * DH];          // WqT @ bk
__device__ float g_b2  [DH];              // bq @ Wk
__device__ float g_cq;                    // bk . bq
__device__ int   g_em  [NN];
__device__ int   g_acc_cnt;

// ---------------------------------------------------------------------------
// Kernel 1: W2 = WqT @ Wk (blocks 0-31) + vec/init/bl0 work (block 32)
// ---------------------------------------------------------------------------
__global__ __launch_bounds__(256)
void w2v_kernel(const float* __restrict__ Wq, const float* __restrict__ Wk,
                const float* __restrict__ bq, const float* __restrict__ bk,
                const float* __restrict__ Wrel) {
    int tid = threadIdx.x;
    if (blockIdx.x == 32) {
        #pragma unroll
        for (int rep = 0; rep < 2; rep++) {
            int k = tid + rep * 256;
            float ua = 0.f;
            for (int d = 0; d < DH; d++)
                ua += __ldg(&bk[d]) * __ldg(&Wq[(size_t)d * (2 * DH) + k]);
            g_u[k] = ua;
            // bl0 row k: cols 0..15 = Wrel[t][k], col 16 = u[k], rest 0
            #pragma unroll
            for (int t = 0; t < NTYP; t++)
                g_bl0[k * 32 + t] = __ldg(&Wrel[(size_t)t * (2 * DH + DX) + k]);
            g_bl0[k * 32 + 16] = ua;
            #pragma unroll
            for (int t = 17; t < 32; t++) g_bl0[k * 32 + t] = 0.f;
        }
        float b2 = 0.f;
        for (int d = 0; d < DH; d++)
            b2 += __ldg(&bq[d]) * __ldg(&Wk[(size_t)d * DH + tid]);
        g_b2[tid] = b2;
        g_em[tid] = 0x7fffffff;
        g_em[tid + 256] = 0x7fffffff;
        if (tid == 0) {
            float c = 0.f;
            for (int d = 0; d < DH; d++) c += __ldg(&bk[d]) * __ldg(&bq[d]);
            g_cq = c;
            g_acc_cnt = 0;
        }
        return;
    }
    __shared__ float s_wq[DH][16];      // [d][kl]
    int k0 = blockIdx.x * 16;
    #pragma unroll
    for (int r = 0; r < 16; r++) {
        int fid = tid + r * 256;        // 0..4095
        int d = fid >> 4, kl = fid & 15;
        s_wq[d][kl] = __ldg(&Wq[(size_t)d * (2 * DH) + k0 + kl]);
    }
    __syncthreads();
    float acc[16] = {};
    int e = tid;
    #pragma unroll 4
    for (int d = 0; d < DH; d++) {
        float wkv = __ldg(&Wk[(size_t)d * DH + e]);
        #pragma unroll
        for (int kl = 0; kl < 16; kl++) acc[kl] += s_wq[d][kl] * wkv;
    }
    #pragma unroll
    for (int kl = 0; kl < 16; kl++)
        g_w2[(size_t)(k0 + kl) * DH + e] = acc[kl];
}

// ---------------------------------------------------------------------------
// Kernel 2: x_sum = segment_sum(tok_emb[mem], grp)  (MLP=4, v4 red)
// ---------------------------------------------------------------------------
#define SC_NT (NMEM * 16 / 4)   // 1,048,576 threads
__global__ __launch_bounds__(256)
void scatter_kernel(const float* __restrict__ tok_emb,
                    const int*   __restrict__ mem,
                    const int*   __restrict__ grp) {
    int t = blockIdx.x * 256 + threadIdx.x;
    int   gg[4], qd[4];
    float4 v[4];
    #pragma unroll
    for (int k = 0; k < 4; k++) {
        int task = t + k * SC_NT;
        int e = task >> 4;
        qd[k] = task & 15;
        int tok = __ldg(&mem[e]);
        gg[k]  = __ldg(&grp[e]);
        v[k] = __ldg(reinterpret_cast<const float4*>(tok_emb) + tok * 16 + qd[k]);
    }
    #pragma unroll
    for (int k = 0; k < 4; k++) {
        float* dst = &g_xsum[(size_t)gg[k] * DX + qd[k] * 4];
        asm volatile("red.global.add.v4.f32 [%0], {%1, %2, %3, %4};"
                     :: "l"(dst), "f"(v[k].x), "f"(v[k].y), "f"(v[k].z), "f"(v[k].w)
                     : "memory");
    }
}

// ---------------------------------------------------------------------------
// Kernel 3: y[r,t] = sum_j x_sum[r,j] * Wrel[t, 512+j]   (32768 x 16)
// one thread per row. 128 blocks x 256 threads.
// ---------------------------------------------------------------------------
__global__ __launch_bounds__(256)
void y_kernel(const float* __restrict__ Wrel) {
    __shared__ float wx[NTYP][DX];
    int tid = threadIdx.x;
    #pragma unroll
    for (int r = 0; r < 4; r++) {
        int v = tid + r * 256;
        int t = v >> 6, j = v & 63;
        wx[t][j] = __ldg(&Wrel[(size_t)t * (2 * DH + DX) + 2 * DH + j]);
    }
    __syncthreads();

    int row = blockIdx.x * 256 + tid;
    const float4* x4 = reinterpret_cast<const float4*>(g_xsum + (size_t)row * DX);
    float acc[NTYP] = {};
    #pragma unroll
    for (int j4 = 0; j4 < 16; j4++) {
        float4 x = x4[j4];
        int j = j4 * 4;
        #pragma unroll
        for (int t = 0; t < NTYP; t++)
            acc[t] += x.x * wx[t][j] + x.y * wx[t][j + 1] + x.z * wx[t][j + 2] + x.w * wx[t][j + 3];
    }
    float4* yo = reinterpret_cast<float4*>(g_y + (size_t)row * NTYP);
    #pragma unroll
    for (int t4 = 0; t4 < 4; t4++)
        yo[t4] = make_float4(acc[t4 * 4], acc[t4 * 4 + 1], acc[t4 * 4 + 2], acc[t4 * 4 + 3]);
}

// ---------------------------------------------------------------------------
// Kernel 4: TF32 tensor-core gather-GEMM: wv = q_in @ W2 + b2  (unchanged)
// ---------------------------------------------------------------------------
#define AS_STRIDE 36
#define BS_STRIDE 136
#define GEMM_SMEM_FLOATS (2 * 128 * AS_STRIDE + 2 * 32 * BS_STRIDE + 2 * 128)
#define GEMM_SMEM_BYTES  (GEMM_SMEM_FLOATS * 4)

__device__ __forceinline__ void mma_tf32(float* c, const uint32_t* a, const uint32_t* b) {
    asm volatile(
        "mma.sync.aligned.m16n8k8.row.col.f32.tf32.tf32.f32 "
        "{%0,%1,%2,%3}, {%4,%5,%6,%7}, {%8,%9}, {%0,%1,%2,%3};"
        : "+f"(c[0]), "+f"(c[1]), "+f"(c[2]), "+f"(c[3])
        : "r"(a[0]), "r"(a[1]), "r"(a[2]), "r"(a[3]), "r"(b[0]), "r"(b[1]));
}

__global__ __launch_bounds__(256)
void gemm_tf32(const float* __restrict__ h_grp,
               const int* __restrict__ idx,
               const int* __restrict__ src,
               const int* __restrict__ dst) {
    extern __shared__ float dsm[];
    float* As = dsm;                                  // [2][128][AS_STRIDE]
    float* Bs = dsm + 2 * 128 * AS_STRIDE;            // [2][32][BS_STRIDE]
    int*  sOff = (int*)(Bs + 2 * 32 * BS_STRIDE);     // [2][128]

    const int tid  = threadIdx.x;
    const int lane = tid & 31;
    const int w    = tid >> 5;
    const int wm   = (w >> 2) * 64;
    const int wn   = (w & 3) * 32;
    const int row0 = blockIdx.y * 128;
    const int col0 = blockIdx.x * 128;

    if (tid < 128) {
        int q = row0 + tid;
        int i = __ldg(&idx[q]);
        sOff[tid]       = (i * LL + __ldg(&src[q])) * DH;
        sOff[128 + tid] = (i * LL + __ldg(&dst[q])) * DH;
    }
    __syncthreads();

    const int amr = tid >> 3;
    const int ac4 = (tid & 7) * 4;
    const int bkr = tid >> 5;
    const int bn4 = (tid & 31) * 4;

    float4 rA[4], rB[4];
    auto ldgChunk = [&](int ch) {
        int kb = ch * 32;
        const int* off = sOff + ((kb >> 8) << 7);
        int kbl = kb & 255;
        #pragma unroll
        for (int j = 0; j < 4; j++)
            rA[j] = *reinterpret_cast<const float4*>(h_grp + off[amr + 32 * j] + kbl + ac4);
        #pragma unroll
        for (int j = 0; j < 4; j++)
            rB[j] = *reinterpret_cast<const float4*>(&g_w2[(size_t)(kb + bkr + 8 * j) * DH + col0 + bn4]);
    };
    auto stsChunk = [&](int buf) {
        float* a = As + buf * 128 * AS_STRIDE;
        float* b = Bs + buf * 32 * BS_STRIDE;
        #pragma unroll
        for (int j = 0; j < 4; j++)
            *reinterpret_cast<float4*>(a + (amr + 32 * j) * AS_STRIDE + ac4) = rA[j];
        #pragma unroll
        for (int j = 0; j < 4; j++)
            *reinterpret_cast<float4*>(b + (bkr + 8 * j) * BS_STRIDE + bn4) = rB[j];
    };

    float acc[4][4][4] = {};
    ldgChunk(0); stsChunk(0); __syncthreads();

    for (int t = 0; t < 16; t++) {
        int buf = t & 1;
        if (t < 15) ldgChunk(t + 1);
        const float* a = As + buf * 128 * AS_STRIDE;
        const float* b = Bs + buf * 32 * BS_STRIDE;
        const int ar = wm + (lane >> 2);
        const int bn = wn + (lane >> 2);
        #pragma unroll
        for (int ks = 0; ks < 4; ks++) {
            int kc = ks * 8 + (lane & 3);
            uint32_t af[4][4], bf[4][2];
            #pragma unroll
            for (int mt = 0; mt < 4; mt++) {
                const float* ap = a + (ar + mt * 16) * AS_STRIDE + kc;
                af[mt][0] = __float_as_uint(ap[0]);
                af[mt][1] = __float_as_uint(ap[8 * AS_STRIDE]);
                af[mt][2] = __float_as_uint(ap[4]);
                af[mt][3] = __float_as_uint(ap[8 * AS_STRIDE + 4]);
            }
            #pragma unroll
            for (int nt = 0; nt < 4; nt++) {
                const float* bp = b + kc * BS_STRIDE + bn + nt * 8;
                bf[nt][0] = __float_as_uint(bp[0]);
                bf[nt][1] = __float_as_uint(bp[4 * BS_STRIDE]);
            }
            #pragma unroll
            for (int mt = 0; mt < 4; mt++)
                #pragma unroll
                for (int nt = 0; nt < 4; nt++)
                    mma_tf32(acc[mt][nt], af[mt], bf[nt]);
        }
        if (t < 15) { stsChunk(buf ^ 1); __syncthreads(); }
    }

    #pragma unroll
    for (int mt = 0; mt < 4; mt++) {
        int r = row0 + wm + mt * 16 + (lane >> 2);
        #pragma unroll
        for (int nt = 0; nt < 4; nt++) {
            int cb = col0 + wn + nt * 8 + (lane & 3) * 2;
            float b0 = __ldg(&g_b2[cb]);
            float b1 = __ldg(&g_b2[cb + 1]);
            *reinterpret_cast<float2*>(&g_wv[(size_t)r * DH + cb]) =
                make_float2(acc[mt][nt][0] + b0, acc[mt][nt][1] + b1);
            *reinterpret_cast<float2*>(&g_wv[(size_t)(r + 8) * DH + cb]) =
                make_float2(acc[mt][nt][2] + b0, acc[mt][nt][3] + b1);
        }
    }
}

// ---------------------------------------------------------------------------
// Kernel 5: fp32 gather-GEMM l0 = q_in @ bl0  (8192x512x32)
// BM=128, BN=32, BK=32, 256 threads, 8x2 microtile. grid 64.
// ---------------------------------------------------------------------------
#define L0_AS  132   // [32][132]
#define L0_BS  33    // [32][33]
__global__ __launch_bounds__(256)
void l0_gemm(const float* __restrict__ h_grp,
             const int* __restrict__ idx,
             const int* __restrict__ src,
             const int* __restrict__ dst) {
    __shared__ float As[32 * L0_AS];
    __shared__ float Bs[32 * L0_BS];
    __shared__ int   sOff[2 * 128];

    const int tid  = threadIdx.x;
    const int row0 = blockIdx.x * 128;

    if (tid < 128) {
        int q = row0 + tid;
        int i = __ldg(&idx[q]);
        sOff[tid]       = (i * LL + __ldg(&src[q])) * DH;
        sOff[128 + tid] = (i * LL + __ldg(&dst[q])) * DH;
    }
    __syncthreads();

    const int ty = tid >> 4;           // 0..15 -> 8 rows each
    const int tx = tid & 15;           // 0..15 -> 2 cols each
    float acc[8][2] = {};

    const int amr = tid >> 3;          // 0..31 (+32 per j)
    const int ac4 = (tid & 7) * 4;
    const int bkr = tid >> 3;          // 0..31
    const int bc4 = (tid & 7) * 4;

    for (int ch = 0; ch < 16; ch++) {
        int kb = ch * 32;
        const int* off = sOff + ((kb >> 8) << 7);
        int kbl = kb & 255;
        float4 rA[4];
        #pragma unroll
        for (int j = 0; j < 4; j++)
            rA[j] = *reinterpret_cast<const float4*>(h_grp + off[amr + 32 * j] + kbl + ac4);
        float4 rB = *reinterpret_cast<const float4*>(&g_bl0[(kb + bkr) * 32 + bc4]);
        __syncthreads();   // protect previous iteration's reads
        #pragma unroll
        for (int j = 0; j < 4; j++) {
            int r = amr + 32 * j;
            As[(ac4 + 0) * L0_AS + r] = rA[j].x;
            As[(ac4 + 1) * L0_AS + r] = rA[j].y;
            As[(ac4 + 2) * L0_AS + r] = rA[j].z;
            As[(ac4 + 3) * L0_AS + r] = rA[j].w;
        }
        Bs[bkr * L0_BS + bc4 + 0] = rB.x;
        Bs[bkr * L0_BS + bc4 + 1] = rB.y;
        Bs[bkr * L0_BS + bc4 + 2] = rB.z;
        Bs[bkr * L0_BS + bc4 + 3] = rB.w;
        __syncthreads();

        #pragma unroll
        for (int k = 0; k < 32; k++) {
            float b0 = Bs[k * L0_BS + tx * 2];
            float b1 = Bs[k * L0_BS + tx * 2 + 1];
            const float* ar = As + k * L0_AS + ty * 8;
            #pragma unroll
            for (int i = 0; i < 8; i++) {
                float av = ar[i];
                acc[i][0] += av * b0;
                acc[i][1] += av * b1;
            }
        }
    }

    #pragma unroll
    for (int i = 0; i < 8; i++) {
        int q = row0 + ty * 8 + i;
        *reinterpret_cast<float2*>(&g_l0[(size_t)q * 32 + tx * 2]) =
            make_float2(acc[i][0], acc[i][1]);
    }
}

// ---------------------------------------------------------------------------
// Kernel 6: block-per-group, warp-per-query attention + logits + metrics.
// ---------------------------------------------------------------------------
__device__ __forceinline__ int lbound(const int* __restrict__ a, int n, int key) {
    int lo = 0, hi = n;
    while (lo < hi) { int m = (lo + hi) >> 1; if (__ldg(&a[m]) < key) lo = m + 1; else hi = m; }
    return lo;
}

#define ATTN_SMEM_FLOATS (16384 + 2048 + 512 + 1024 + 64 + 64 + 16)
#define ATTN_SMEM_BYTES  (ATTN_SMEM_FLOATS * 4)

__global__ __launch_bounds__(256)
void attn_kernel(const float* __restrict__ h_grp,
                 const float* __restrict__ brel,
                 const int*   __restrict__ idx,
                 const int*   __restrict__ src,
                 const int*   __restrict__ dst,
                 const int*   __restrict__ pos2grp,
                 const int*   __restrict__ msk,
                 const int*   __restrict__ typ,
                 float* __restrict__ out_logit) {
    extern __shared__ float sm[];
    float* s_ht  = sm;                    // 16384 : transposed h, s_ht[e*64 + l]
    float* s_wvb = s_ht  + 16384;         // 2048  : per-warp wv (8*256)
    float* s_ab  = s_wvb + 2048;          // 512   : per-warp a (8*64)
    float* s_y   = s_ab  + 512;           // 1024  : y rows [l][16]
    float* s_msk = s_y   + 1024;          // 64
    int*   s_g   = (int*)(s_msk + 64);    // 64
    int*   s_acc = s_g + 64;              // 8
    int*   s_em  = s_acc + 8;             // 8

    const int n    = blockIdx.x;
    const int tid  = threadIdx.x;     // 256
    const int lane = tid & 31;
    const int w    = tid >> 5;        // 8 warps

    const int lo = lbound(idx, QQ, n);
    const int hi = lbound(idx, QQ, n + 1);
    if (lo >= hi) return;

    // stage h transposed (conflict-free STS)
    {
        const float4* hb4 = reinterpret_cast<const float4*>(h_grp + (size_t)n * LL * DH);
        #pragma unroll
        for (int k = 0; k < 16; k++) {
            int v = tid + k * 256;
            int l = v & 63, e4 = v >> 6;
            float4 hv = __ldg(hb4 + l * 64 + e4);
            int e = e4 * 4;
            s_ht[(e + 0) * 64 + l] = hv.x;
            s_ht[(e + 1) * 64 + l] = hv.y;
            s_ht[(e + 2) * 64 + l] = hv.z;
            s_ht[(e + 3) * 64 + l] = hv.w;
        }
    }
    if (tid < LL) {
        s_g[tid]   = __ldg(&pos2grp[n * LL + tid]);
        s_msk[tid] = (__ldg(&msk[n * LL + tid]) == 0) ? -INFINITY : 0.f;
    }
    __syncthreads();

    // gather y rows (64 x 16)
    #pragma unroll
    for (int k = 0; k < 4; k++) {
        int v = tid + k * 256;
        int l = v >> 4, t = v & 15;
        s_y[l * 16 + t] = __ldg(&g_y[(size_t)s_g[l] * NTYP + t]);
    }
    __syncthreads();

    int accW = 0, emW = 1;
    const float2* ht2 = reinterpret_cast<const float2*>(s_ht);
    float* wvp = s_wvb + w * 256;
    float* abp = s_ab  + w * 64;
    const float mk0 = s_msk[2 * lane];
    const float mk1 = s_msk[2 * lane + 1];
    const int tt = lane & 15;
    const float brl = __ldg(&brel[tt]);

    for (int q = lo + w; q < hi; q += 8) {
        // stage wv
        const float4* wv4 = reinterpret_cast<const float4*>(g_wv + (size_t)q * DH);
        reinterpret_cast<float4*>(wvp)[lane]      = __ldg(wv4 + lane);
        reinterpret_cast<float4*>(wvp)[32 + lane] = __ldg(wv4 + 32 + lane);
        __syncwarp();

        const float c = __ldg(&g_l0[(size_t)q * 32 + 16]) + g_cq;

        // scores for rows 2*lane, 2*lane+1 (4 independent chains)
        float p0a = 0.f, p0b = 0.f, p1a = 0.f, p1b = 0.f;
        #pragma unroll 4
        for (int e = 0; e < DH; e += 2) {
            float wva = wvp[e], wvb = wvp[e + 1];
            float2 ha = ht2[e * 32 + lane];
            float2 hb = ht2[(e + 1) * 32 + lane];
            p0a += ha.x * wva; p1a += ha.y * wva;
            p0b += hb.x * wvb; p1b += hb.y * wvb;
        }
        float v0 = (p0a + p0b + c) * 0.0625f + mk0;
        float v1 = (p1a + p1b + c) * 0.0625f + mk1;

        // warp softmax over 64
        float mmx = fmaxf(v0, v1);
        #pragma unroll
        for (int o = 16; o > 0; o >>= 1) mmx = fmaxf(mmx, __shfl_xor_sync(0xffffffffu, mmx, o));
        float e0 = __expf(v0 - mmx), e1 = __expf(v1 - mmx);
        float ssum = e0 + e1;
        #pragma unroll
        for (int o = 16; o > 0; o >>= 1) ssum += __shfl_xor_sync(0xffffffffu, ssum, o);
        float inv = 1.f / ssum;
        reinterpret_cast<float2*>(abp)[lane] = make_float2(e0 * inv, e1 * inv);
        __syncwarp();

        // logit[t] = l0[q][t] + sum_l a[l]*y[l][t] + brel[t]  (lanes 0..15, dup 16..31)
        float pa = 0.f, pb = 0.f;
        #pragma unroll 8
        for (int l = 0; l < LL; l += 2) {
            pa += abp[l]     * s_y[l * 16 + tt];
            pb += abp[l + 1] * s_y[(l + 1) * 16 + tt];
        }
        float logit = pa + pb + __ldg(&g_l0[(size_t)q * 32 + tt]) + brl;
        if (lane < 16) out_logit[(size_t)q * NTYP + tt] = logit;

        int gt = (logit > 0.f) ? 1 : 0;
        int ty = (__ldg(&typ[q * NTYP + tt]) > 0) ? 1 : 0;
        unsigned m = __ballot_sync(0xffffffffu, gt == ty) & 0xFFFFu;
        if (lane == 0) {
            accW += __popc(m);
            emW &= (m == 0xFFFFu) ? 1 : 0;
        }
    }

    if (lane == 0) { s_acc[w] = accW; s_em[w] = emW; }
    __syncthreads();
    if (tid == 0) {
        int a = 0, e = 1;
        #pragma unroll
        for (int r = 0; r < 8; r++) { a += s_acc[r]; e &= s_em[r]; }
        atomicAdd(&g_acc_cnt, a);
        g_em[n] = e;
    }
}

// ---------------------------------------------------------------------------
// Kernel 7: finalize scalars. out layout: [logit(131072), acc, emr, em(512)]
// ---------------------------------------------------------------------------
__global__ __launch_bounds__(512)
void finalize_kernel(float* __restrict__ out) {
    __shared__ float s_red[16];
    int tid = threadIdx.x;            // 512
    int lane = tid & 31, w = tid >> 5;
    float e = (float)g_em[tid];
    out[QQ * NTYP + 2 + tid] = e;
    float p = e;
    #pragma unroll
    for (int o = 16; o > 0; o >>= 1) p += __shfl_xor_sync(0xffffffffu, p, o);
    if (lane == 0) s_red[w] = p;
    __syncthreads();
    if (tid == 0) {
        float sum = 0.f;
        #pragma unroll
        for (int r = 0; r < 16; r++) sum += s_red[r];
        out[QQ * NTYP + 0] = (float)g_acc_cnt / (float)(QQ * NTYP);
        out[QQ * NTYP + 1] = sum / (float)NN;
    }
}

// ---------------------------------------------------------------------------
extern "C" void kernel_launch(void* const* d_in, const int* in_sizes, int n_in,
                              void* d_out, int out_size) {
    const float* h_grp   = (const float*)d_in[0];
    const float* tok_emb = (const float*)d_in[1];
    const float* Wq      = (const float*)d_in[2];
    const float* bq      = (const float*)d_in[3];
    const float* Wk      = (const float*)d_in[4];
    const float* bk      = (const float*)d_in[5];
    const float* Wrel    = (const float*)d_in[6];
    const float* brel    = (const float*)d_in[7];
    const int*   mem     = (const int*)d_in[8];
    const int*   grp     = (const int*)d_in[9];
    const int*   pos2grp = (const int*)d_in[10];
    const int*   msk     = (const int*)d_in[11];
    const int*   idx     = (const int*)d_in[12];
    const int*   src     = (const int*)d_in[13];
    const int*   dst     = (const int*)d_in[14];
    const int*   typ     = (const int*)d_in[15];
    float* out = (float*)d_out;

    float* xsum_ptr; cudaGetSymbolAddress((void**)&xsum_ptr, g_xsum);

    // memset node (not a kernel launch)
    cudaMemsetAsync(xsum_ptr, 0, (size_t)NSEG * DX * sizeof(float));

    // kernel #1: W2 + vec + init + bl0
    w2v_kernel<<<33, 256>>>(Wq, Wk, bq, bk, Wrel);

    // kernel #2: segment-sum scatter
    scatter_kernel<<<SC_NT / 256, 256>>>(tok_emb, mem, grp);

    // kernel #3: y = x_sum @ Wrel_x^T
    y_kernel<<<NSEG / 256, 256>>>(Wrel);

    // kernel #4 (ncu slot): TF32 tensor-core gather-GEMM wv
    {
        cudaFuncSetAttribute(gemm_tf32, cudaFuncAttributeMaxDynamicSharedMemorySize, GEMM_SMEM_BYTES);
        dim3 grid(DH / 128, QQ / 128);
        gemm_tf32<<<grid, 256, GEMM_SMEM_BYTES>>>(h_grp, idx, src, dst);
    }

    // kernel #5: fp32 l0 GEMM (logit q_in part + c column)
    l0_gemm<<<QQ / 128, 256>>>(h_grp, idx, src, dst);

    // kernel #6: attention + logits + metrics
    cudaFuncSetAttribute(attn_kernel, cudaFuncAttributeMaxDynamicSharedMemorySize, ATTN_SMEM_BYTES);
    attn_kernel<<<NN, 256, ATTN_SMEM_BYTES>>>(h_grp, brel, idx, src, dst,
                                              pos2grp, msk, typ, out);

    // kernel #7: finalize
    finalize_kernel<<<1, 512>>>(out);
}